// round 17
// baseline (speedup 1.0000x reference)
#include <cuda_runtime.h>
#include <cuda_bf16.h>
#include <cub/cub.cuh>
#include <math_constants.h>

// FrechetSort: per row (B=4096, N=8192):
//   perturbed = scores - log(-log(gumbel_u))   (XLA:CPU GenerateVF32Log, aarch64-contracted — LOCKED)
//   action    = argsort(-perturbed)  (descending, stable)
//   log_proba = sum_r (x_r - suffix_logsumexp(x)_r),  x = scores[action]
// Output (float32): [action (B*N) | log_proba (B)]
//
// Sort: cub::BlockRadixSort<u32,512,16,u16,RADIX_BITS=6> — 6 passes,
// __launch_bounds__(512, 2) => two CTAs co-resident per SM (rank smem
// 64 KB/CTA, 128 KB total — still fits).

static constexpr int N_COLS  = 8192;
static constexpr int BLOCK_T = 512;
static constexpr int ITEMS   = 16;   // 512*16 = 8192
static constexpr int NWARP   = BLOCK_T / 32;   // 16
static constexpr int RBITS   = 6;    // 6 passes: 6*5 + 2

using BlockRadixSortT =
    cub::BlockRadixSort<unsigned int, BLOCK_T, ITEMS, unsigned short, RBITS>;

struct Smem {
    union {
        typename BlockRadixSortT::TempStorage sort;
        float scores[N_COLS];
    } u;
    float warp_red[NWARP];
};

// XLA GenerateVF32Log, aarch64 backend contraction. Positive normal x. (LOCKED — R11)
__device__ __forceinline__ float xla_vf32_logf(float xin) {
    unsigned int bits = __float_as_uint(xin);
    float e = (float)((int)(bits >> 23) - 126);
    float m = __uint_as_float((bits & 0x007fffffu) | 0x3f000000u);

    const float SQRTHF = 0.707106781186547524f;
    bool mask = m < SQRTHF;
    float tmp = mask ? m : 0.0f;
    m = __fadd_rn(m, -1.0f);
    e = __fadd_rn(e, mask ? -1.0f : 0.0f);
    m = __fadd_rn(m, tmp);

    float z = __fmul_rn(m, m);

    float y = 7.0376836292e-2f;
    y = __fmaf_rn(y, m, -1.1514610310e-1f);
    y = __fmaf_rn(y, m,  1.1676998740e-1f);
    y = __fmaf_rn(y, m, -1.2420140846e-1f);
    y = __fmaf_rn(y, m,  1.4249322787e-1f);
    y = __fmaf_rn(y, m, -1.6668057665e-1f);
    y = __fmaf_rn(y, m,  2.0000714765e-1f);
    y = __fmaf_rn(y, m, -2.4999993993e-1f);
    y = __fmaf_rn(y, m,  3.3333331174e-1f);
    y = __fmul_rn(y, m);
    y = __fmul_rn(y, z);

    y = __fmaf_rn(e, -2.12194440e-4f, y);   // y += e*q1
    m = __fmaf_rn(-0.5f, z, m);             // m -= z*0.5  (into m — XLA association)
    m = __fadd_rn(m, y);
    m = __fmaf_rn(e, 0.693359375f, m);      // m += e*q2
    return m;
}

__device__ __forceinline__ float lae(float a, float b) {
    float mx = fmaxf(a, b);
    float mn = fminf(a, b);
    if (mn == -CUDART_INF_F) return mx;
    return mx + log1pf(expf(mn - mx));
}

__global__ __launch_bounds__(BLOCK_T, 2)
void frechet_sort_kernel(const float* __restrict__ scores,
                         const float* __restrict__ gumbel_u,
                         float* __restrict__ out,
                         int n_rows, int write_logp)
{
    extern __shared__ unsigned char smem_raw[];
    Smem& sm = *reinterpret_cast<Smem*>(smem_raw);

    const int row  = blockIdx.x;
    if (row >= n_rows) return;
    const long long base = (long long)row * N_COLS;
    const int t    = threadIdx.x;
    const int lane = t & 31;
    const int warp = t >> 5;
    const unsigned FULL = 0xFFFFFFFFu;

    // ---- 1. Load + compute keys (blocked: thread t owns [t*16, t*16+16)) ----
    unsigned int   keys[ITEMS];
    unsigned short vals[ITEMS];
    {
        const int i0 = t * ITEMS;
        const float4* s4 = reinterpret_cast<const float4*>(scores   + base + i0);
        const float4* g4 = reinterpret_cast<const float4*>(gumbel_u + base + i0);
        #pragma unroll
        for (int q = 0; q < ITEMS / 4; q++) {
            float4 a = s4[q];
            float4 b = g4[q];
            float s[4] = {a.x, a.y, a.z, a.w};
            float g[4] = {b.x, b.y, b.z, b.w};
            #pragma unroll
            for (int c = 0; c < 4; c++) {
                int j = q * 4 + c;
                float t1 = xla_vf32_logf(g[c]);       // log(u)  (negative)
                float t3 = xla_vf32_logf(-t1);        // log(-log(u))
                float pert = __fadd_rn(s[c], -t3);    // scores + gumbel
                unsigned int m = __float_as_uint(pert);
                m = (m & 0x80000000u) ? ~m : (m | 0x80000000u);
                keys[j] = ~m;                         // ascending key == descending pert
                vals[j] = (unsigned short)(i0 + j);
            }
        }
    }

    // ---- 2. Stable block radix sort (6-bit digits, 6 passes) ----
    BlockRadixSortT(sm.u.sort).Sort(keys, vals);
    __syncthreads();

    // ---- 3. Write action (blocked: thread t owns ranks [t*16, t*16+16)) ----
    {
        const int r0 = t * ITEMS;
        float4* o4 = reinterpret_cast<float4*>(out + base + r0);
        #pragma unroll
        for (int q = 0; q < ITEMS / 4; q++) {
            float4 o;
            o.x = (float)vals[q*4+0]; o.y = (float)vals[q*4+1];
            o.z = (float)vals[q*4+2]; o.w = (float)vals[q*4+3];
            o4[q] = o;
        }
    }

    if (!write_logp) return;

    // ---- 4. Stage scores in smem, gather x in rank order ----
    for (int i = t; i < N_COLS; i += BLOCK_T)
        sm.u.scores[i] = scores[base + i];
    __syncthreads();

    float x[ITEMS];
    #pragma unroll
    for (int j = 0; j < ITEMS; j++)
        x[j] = sm.u.scores[vals[j]];

    // ---- 5. Suffix logsumexp over ranks ----
    float lsuf[ITEMS];
    lsuf[ITEMS - 1] = x[ITEMS - 1];
    #pragma unroll
    for (int j = ITEMS - 2; j >= 0; j--)
        lsuf[j] = lae(x[j], lsuf[j + 1]);
    const float tot = lsuf[0];

    // Warp inclusive suffix scan of thread totals (over 32 lanes)
    float incl = tot;
    #pragma unroll
    for (int off = 1; off < 32; off <<= 1) {
        float v = __shfl_down_sync(FULL, incl, off);
        if (lane + off < 32) incl = lae(incl, v);
    }
    if (lane == 0) sm.warp_red[warp] = incl;   // warp total
    __syncthreads();
    if (warp == 0 && lane < NWARP) {
        float wincl = sm.warp_red[lane];
        #pragma unroll
        for (int off = 1; off < NWARP; off <<= 1) {
            float v = __shfl_down_sync(0x0000FFFFu, wincl, off);
            if (lane + off < NWARP) wincl = lae(wincl, v);
        }
        float wexcl = __shfl_down_sync(0x0000FFFFu, wincl, 1);
        if (lane == NWARP - 1) wexcl = -CUDART_INF_F;
        sm.warp_red[lane] = wexcl;   // exclusive suffix of warp totals
    }
    __syncthreads();

    float exclWithin = __shfl_down_sync(FULL, incl, 1);
    if (lane == 31) exclWithin = -CUDART_INF_F;
    const float sufExcl = lae(exclWithin, sm.warp_red[warp]);

    float acc = 0.0f;
    #pragma unroll
    for (int j = 0; j < ITEMS; j++)
        acc += x[j] - lae(lsuf[j], sufExcl);

    // ---- 6. Block reduce -> log_proba[row] ----
    #pragma unroll
    for (int off = 16; off > 0; off >>= 1)
        acc += __shfl_down_sync(FULL, acc, off);
    __syncthreads();
    if (lane == 0) sm.warp_red[warp] = acc;
    __syncthreads();
    if (warp == 0 && lane < NWARP) {
        float v = sm.warp_red[lane];
        #pragma unroll
        for (int off = NWARP / 2; off > 0; off >>= 1)
            v += __shfl_down_sync(0x0000FFFFu, v, off);
        if (lane == 0)
            out[(long long)n_rows * N_COLS + row] = v;
    }
}

extern "C" void kernel_launch(void* const* d_in, const int* in_sizes, int n_in,
                              void* d_out, int out_size)
{
    const float* scores   = (const float*)d_in[0];
    const float* gumbel_u = (const float*)d_in[1];
    float* out = (float*)d_out;

    const int total = in_sizes[0];
    const int n_rows = total / N_COLS;
    const int write_logp = (out_size >= total + n_rows) ? 1 : 0;

    const size_t shbytes = sizeof(Smem);
    cudaFuncSetAttribute(frechet_sort_kernel,
                         cudaFuncAttributeMaxDynamicSharedMemorySize, (int)shbytes);

    frechet_sort_kernel<<<n_rows, BLOCK_T, shbytes>>>(scores, gumbel_u, out, n_rows, write_logp);
}